// round 12
// baseline (speedup 1.0000x reference)
#include <cuda_runtime.h>
#include <cuda_fp16.h>
#include <math.h>
#include <stdint.h>

#define D      128
#define NGRAPH 64
#define LROWS  2048
#define EPS    1e-8f
#define YSCALE 0.015625f   // 2^-6, exact

// ---------------------------------------------------------------------------
// Global scratch. Fully consistent rounded pipeline:
//   x~ = rn(x); G~ = rn(X~^T X~); W~ = rn(w^2)
//   out = cosine computed exactly (fp32 accum) from x~, G~, W~.
// ---------------------------------------------------------------------------
__device__ float  g_grams[2 * NGRAPH * D * D];   // two split-K partials
__device__ __half g_gh[NGRAPH * D * D];
__device__ __half g_wh[D * D];

// ---------------------------------------------------------------------------
// Helpers
// ---------------------------------------------------------------------------
__device__ __forceinline__ uint32_t smem_to_u32(const void* p) {
    uint32_t a;
    asm("{ .reg .u64 t; cvta.to.shared.u64 t, %1; cvt.u32.u64 %0, t; }" : "=r"(a) : "l"(p));
    return a;
}
__device__ __forceinline__ uint32_t h2u(__half2 h) { return *(uint32_t*)&h; }

__device__ __forceinline__ void ldsm4(uint32_t* r, uint32_t addr) {
    asm volatile("ldmatrix.sync.aligned.m8n8.x4.shared.b16 {%0,%1,%2,%3}, [%4];"
        : "=r"(r[0]), "=r"(r[1]), "=r"(r[2]), "=r"(r[3]) : "r"(addr));
}
__device__ __forceinline__ void ldsm4t(uint32_t* r, uint32_t addr) {
    asm volatile("ldmatrix.sync.aligned.m8n8.x4.trans.shared.b16 {%0,%1,%2,%3}, [%4];"
        : "=r"(r[0]), "=r"(r[1]), "=r"(r[2]), "=r"(r[3]) : "r"(addr));
}
__device__ __forceinline__ void stsm4(uint32_t addr, const uint32_t* r) {
    asm volatile("stmatrix.sync.aligned.m8n8.x4.shared.b16 [%0], {%1,%2,%3,%4};"
        :: "r"(addr), "r"(r[0]), "r"(r[1]), "r"(r[2]), "r"(r[3]) : "memory");
}
__device__ __forceinline__ void mma16816(float* c, const uint32_t* a, const uint32_t* b) {
    asm volatile("mma.sync.aligned.m16n8k16.row.col.f32.f16.f16.f32 "
        "{%0,%1,%2,%3}, {%4,%5,%6,%7}, {%8,%9}, {%0,%1,%2,%3};"
        : "+f"(c[0]), "+f"(c[1]), "+f"(c[2]), "+f"(c[3])
        : "r"(a[0]), "r"(a[1]), "r"(a[2]), "r"(a[3]), "r"(b[0]), "r"(b[1]));
}

// ---------------------------------------------------------------------------
__global__ void wcvt_kernel(const float* __restrict__ mp_w) {
    int idx = blockIdx.x * blockDim.x + threadIdx.x;
    if (idx >= D * D) return;
    float v = mp_w[idx];
    g_wh[idx] = __float2half_rn(v * v);
}

__global__ void gram_cvt_kernel() {
    int idx = blockIdx.x * blockDim.x + threadIdx.x;
    if (idx >= NGRAPH * D * D / 4) return;
    float4 a = *(const float4*)(g_grams + 4 * (size_t)idx);
    float4 b = *(const float4*)(g_grams + NGRAPH * D * D + 4 * (size_t)idx);
    __half2 h01 = __floats2half2_rn(a.x + b.x, a.y + b.y);
    __half2 h23 = __floats2half2_rn(a.z + b.z, a.w + b.w);
    *(uint2*)(g_gh + 4 * (size_t)idx) = make_uint2(h2u(h01), h2u(h23));
}

// ---------------------------------------------------------------------------
// HMMA Gram kernel (fp16, 1-pass): G~[g] = X~_g^T X~_g.
// 128 blocks, K=1024 each, fp32 accumulate, partial sums (no atomics).
// ---------------------------------------------------------------------------
#define GSROW 136

__global__ __launch_bounds__(256) void gram_mma_kernel(const float* __restrict__ feats) {
    __shared__ __half sXH[64 * GSROW];
    const uint32_t sbh = smem_to_u32(sXH);

    const int tid  = threadIdx.x;
    const int w    = tid >> 5;
    const int lane = tid & 31;
    const int graph = blockIdx.x >> 1;
    const int split = blockIdx.x & 1;
    const int m0   = w * 16;

    const float* Xg = feats + ((size_t)graph * LROWS + (size_t)split * 1024) * D;

    const int g   = lane >> 3;
    const int li  = lane & 7;
    const uint32_t arl  = (uint32_t)((g >> 1) * 8 + li);
    const uint32_t acol = (uint32_t)(m0 + (g & 1) * 8);
    const uint32_t brl  = (uint32_t)((g & 1) * 8 + li);
    const uint32_t bct  = (uint32_t)(g >> 1);

    float acc[16][4];
#pragma unroll
    for (int t = 0; t < 16; t++)
#pragma unroll
        for (int v = 0; v < 4; v++) acc[t][v] = 0.f;

    for (int chunk = 0; chunk < 16; chunk++) {
        const float4* xs = (const float4*)(Xg + (size_t)chunk * 64 * D);
#pragma unroll
        for (int q = 0; q < 8; q++) {
            int idx = tid + 256 * q;
            int row = idx >> 5, c4 = idx & 31;
            float4 f = xs[idx];
            __half2 h01 = __floats2half2_rn(f.x, f.y);
            __half2 h23 = __floats2half2_rn(f.z, f.w);
            uint32_t off = (uint32_t)(row * GSROW + 4 * c4) * 2;
            *(uint2*)((char*)sXH + off) = make_uint2(h2u(h01), h2u(h23));
        }
        __syncthreads();

#pragma unroll
        for (int j = 0; j < 4; j++) {
            uint32_t aoff = ((j * 16 + arl) * GSROW + acol) * 2;
            uint32_t ah[4];
            ldsm4t(ah, sbh + aoff);
#pragma unroll
            for (int tp = 0; tp < 8; tp++) {
                uint32_t boff = ((j * 16 + brl) * GSROW + (2 * tp + bct) * 8) * 2;
                uint32_t bh[4];
                ldsm4t(bh, sbh + boff);
                mma16816(acc[2 * tp],     ah, bh);
                mma16816(acc[2 * tp + 1], ah, bh + 2);
            }
        }
        __syncthreads();
    }

    float* G = g_grams + ((size_t)split * NGRAPH + graph) * D * D;
    const int ra = lane >> 2;
    const int ca = (lane & 3) * 2;
#pragma unroll
    for (int t = 0; t < 16; t++) {
        int col = t * 8 + ca;
        *(float2*)&G[(m0 + ra) * D + col]     = make_float2(acc[t][0], acc[t][1]);
        *(float2*)&G[(m0 + ra + 8) * D + col] = make_float2(acc[t][2], acc[t][3]);
    }
}

// ---------------------------------------------------------------------------
// HMMA fused match kernel (fp16, all single-pass): 32 rows/block, 256 thr,
// 2 blocks/SM. Warp w: mt = w>>2 (m16 tile), nq = w&3 (32-col quarter).
// Phase1: Y = X~ * G~ (1-pass). Products in fragment layout from x~ frags.
// Phase2: num = PN*W~, n1 = P1*W~, n2 = P2*W~ (1-pass each).
// ---------------------------------------------------------------------------
#define SROW    136
#define OFF_XH  0u          //  8704 B  -> PN after products (stsm in place)
#define OFF_BH  8704u       // 34816 B  (G~, then W~)
#define OFF_P1H 43520u      //  8704 B
#define OFF_P2H 52224u      //  8704 B
#define SMEM_NEED 60928

__global__ __launch_bounds__(256, 2) void match_mma_kernel(
    const float* __restrict__ feats, float* __restrict__ out) {
    extern __shared__ __align__(16) char smem[];
    const uint32_t sb = smem_to_u32(smem);

    const int tid  = threadIdx.x;
    const int w    = tid >> 5;
    const int lane = tid & 31;
    const int mt   = w >> 2;       // m16 tile 0..1
    const int nq   = w & 3;        // n quarter (32 cols)
    const int r0   = blockIdx.x * 32;
    const int gi   = r0 >> 11;

    const uint2* ghp = (const uint2*)(g_gh + (size_t)(gi ^ 1) * D * D);
    const uint2* whp = (const uint2*)g_wh;

    // ---- stage X~ : 1024 float4, 4 per thread ----
    {
        const float4* xs = (const float4*)(feats + (size_t)r0 * D);
#pragma unroll
        for (int q = 0; q < 4; q++) {
            int idx = tid + 256 * q;
            int row = idx >> 5, c4 = idx & 31;
            float4 f = xs[idx];
            __half2 h01 = __floats2half2_rn(f.x, f.y);
            __half2 h23 = __floats2half2_rn(f.z, f.w);
            uint32_t off = (uint32_t)(row * SROW + 4 * c4) * 2;
            *(uint2*)(smem + OFF_XH + off) = make_uint2(h2u(h01), h2u(h23));
        }
    }
    // ---- stage G~ : 4096 uint2, 16 per thread ----
#pragma unroll
    for (int q = 0; q < 16; q++) {
        int pi = tid + 256 * q;
        int row = pi >> 5, cp2 = pi & 31;
        uint32_t off = (uint32_t)(row * SROW + 4 * cp2) * 2;
        *(uint2*)(smem + OFF_BH + off) = ghp[pi];
    }
    __syncthreads();

    // fragment lane offsets
    const uint32_t arow = mt * 16 + (lane & 7) + ((lane >> 3) & 1) * 8;
    const uint32_t acolh = (lane >> 4) * 8;
    const int g    = lane >> 3;
    const uint32_t bnrow = (uint32_t)((g >> 1) * 8 + (lane & 7));
    const uint32_t bkoff = (uint32_t)((g & 1) * 8);

    // ---------------- Phase 1: Y = X~ * G~ (1-pass) ----------------
    float accY[4][4];
#pragma unroll
    for (int t = 0; t < 4; t++)
#pragma unroll
        for (int v = 0; v < 4; v++) accY[t][v] = 0.f;

#pragma unroll
    for (int j = 0; j < 8; j++) {
        uint32_t aoff = (arow * SROW + j * 16 + acolh) * 2;
        uint32_t ah[4];
        ldsm4(ah, sb + OFF_XH + aoff);
#pragma unroll
        for (int tp = 0; tp < 2; tp++) {
            uint32_t boff = (((uint32_t)(nq * 32 + tp * 16) + bnrow) * SROW + j * 16 + bkoff) * 2;
            uint32_t bh[4];
            ldsm4(bh, sb + OFF_BH + boff);
            mma16816(accY[2 * tp],     ah, bh);
            mma16816(accY[2 * tp + 1], ah, bh + 2);
        }
    }
    __syncthreads();   // all warps done reading G~ and X~ fragments

    // ---- stage W~ (over G~) ----
#pragma unroll
    for (int q = 0; q < 16; q++) {
        int pi = tid + 256 * q;
        int row = pi >> 5, cp2 = pi & 31;
        uint32_t off = (uint32_t)(row * SROW + 4 * cp2) * 2;
        *(uint2*)(smem + OFF_BH + off) = whp[pi];
    }

    // ---- products in fragment layout: warp's cols = X k-chunks 2nq, 2nq+1 ----
    // ldsm reg q: q0=(r,ca), q1=(r+8,ca), q2=(r,ca+8), q3=(r+8,ca+8)
    // accY[t][0..3] = (r,cc),(r,cc+1),(r+8,cc),(r+8,cc+1), cc = nq*32+t*8+ca
#pragma unroll
    for (int c2 = 0; c2 < 2; c2++) {
        int j = 2 * nq + c2;
        uint32_t aoff = (arow * SROW + j * 16 + acolh) * 2;
        uint32_t xh4[4];
        ldsm4(xh4, sb + OFF_XH + aoff);

        uint32_t pnh[4], p1h[4], p2h[4];
#pragma unroll
        for (int q = 0; q < 4; q++) {
            int t  = 2 * c2 + (q >> 1);       // n8 tile
            int rv = (q & 1) * 2;             // 0: rows r, 2: rows r+8
            float2 xhf = __half22float2(*(__half2*)&xh4[q]);
            float x0 = xhf.x, x1 = xhf.y;
            float y0 = accY[t][rv]     * YSCALE;
            float y1 = accY[t][rv + 1] * YSCALE;
            pnh[q] = h2u(__floats2half2_rn(x0 * y0, x1 * y1));
            p1h[q] = h2u(__floats2half2_rn(x0 * x0, x1 * x1));
            p2h[q] = h2u(__floats2half2_rn(y0 * y0, y1 * y1));
        }
        stsm4(sb + OFF_XH + aoff, pnh);    // PN in place over X~
        stsm4(sb + OFF_P1H + aoff, p1h);
        stsm4(sb + OFF_P2H + aoff, p2h);
    }
    __syncthreads();

    // ---------------- Phase 2: num, n1, n2 (1-pass each) ----------------
    float accN[4][4], accB[4][4], accC[4][4];
#pragma unroll
    for (int t = 0; t < 4; t++)
#pragma unroll
        for (int v = 0; v < 4; v++) { accN[t][v] = 0.f; accB[t][v] = 0.f; accC[t][v] = 0.f; }

#pragma unroll
    for (int j = 0; j < 8; j++) {
        uint32_t aoff = (arow * SROW + j * 16 + acolh) * 2;
        uint32_t pn[4], p1[4], p2[4];
        ldsm4(pn, sb + OFF_XH + aoff);
        ldsm4(p1, sb + OFF_P1H + aoff);
        ldsm4(p2, sb + OFF_P2H + aoff);
#pragma unroll
        for (int tp = 0; tp < 2; tp++) {
            uint32_t boff = (((uint32_t)(nq * 32 + tp * 16) + bnrow) * SROW + j * 16 + bkoff) * 2;
            uint32_t wh_[4];
            ldsm4(wh_, sb + OFF_BH + boff);
            mma16816(accN[2 * tp], pn, wh_);
            mma16816(accB[2 * tp], p1, wh_);
            mma16816(accC[2 * tp], p2, wh_);
            mma16816(accN[2 * tp + 1], pn, wh_ + 2);
            mma16816(accB[2 * tp + 1], p1, wh_ + 2);
            mma16816(accC[2 * tp + 1], p2, wh_ + 2);
        }
    }

    // ---------------- Epilogue ----------------
    const int ra = lane >> 2;
    const int ca = (lane & 3) * 2;
#pragma unroll
    for (int t = 0; t < 4; t++) {
        int col = nq * 32 + t * 8 + ca;
#pragma unroll
        for (int h2 = 0; h2 < 2; h2++) {
            int row = r0 + mt * 16 + ra + 8 * h2;
            float n0v = accN[t][2 * h2], n1v = accN[t][2 * h2 + 1];
            float b0v = accB[t][2 * h2], b1v = accB[t][2 * h2 + 1];
            float c0v = accC[t][2 * h2], c1v = accC[t][2 * h2 + 1];
            float2 o;
            o.x = n0v / fmaxf(sqrtf(b0v * c0v), EPS);
            o.y = n1v / fmaxf(sqrtf(b1v * c1v), EPS);
            *(float2*)(out + (size_t)row * D + col) = o;
        }
    }
}

// ---------------------------------------------------------------------------
extern "C" void kernel_launch(void* const* d_in, const int* in_sizes, int n_in,
                              void* d_out, int out_size) {
    const float* feats = (const float*)d_in[0];
    const float* mp_w  = (const float*)d_in[1];
    float* out = (float*)d_out;

    static bool attr_done = false;
    if (!attr_done) {
        cudaFuncSetAttribute(match_mma_kernel,
                             cudaFuncAttributeMaxDynamicSharedMemorySize, SMEM_NEED);
        attr_done = true;
    }

    int N = in_sizes[0] / D;   // 131072 rows

    wcvt_kernel<<<(D * D + 255) / 256, 256>>>(mp_w);
    gram_mma_kernel<<<NGRAPH * 2, 256>>>(feats);
    gram_cvt_kernel<<<(NGRAPH * D * D / 4 + 255) / 256, 256>>>();
    match_mma_kernel<<<N / 32, 256, SMEM_NEED>>>(feats, out);
}

// round 14
// speedup vs baseline: 1.3007x; 1.3007x over previous
#include <cuda_runtime.h>
#include <cuda_fp16.h>
#include <math.h>
#include <stdint.h>

#define D      128
#define NGRAPH 64
#define LROWS  2048
#define EPS    1e-8f
#define YSCALE 0.015625f   // 2^-6, exact

// ---------------------------------------------------------------------------
// Global scratch (hi-only B operands: G and W rounded to fp16, used
// consistently across num/n1/n2 -> near-exact cosine in rounded weights)
// ---------------------------------------------------------------------------
__device__ float  g_grams[2 * NGRAPH * D * D];   // two split-K partials
__device__ __half g_gh[NGRAPH * D * D];
__device__ __half g_wh[D * D];

// ---------------------------------------------------------------------------
// Helpers
// ---------------------------------------------------------------------------
__device__ __forceinline__ uint32_t smem_to_u32(const void* p) {
    uint32_t a;
    asm("{ .reg .u64 t; cvta.to.shared.u64 t, %1; cvt.u32.u64 %0, t; }" : "=r"(a) : "l"(p));
    return a;
}
__device__ __forceinline__ uint32_t h2u(__half2 h) { return *(uint32_t*)&h; }

__device__ __forceinline__ void ldsm4(uint32_t* r, uint32_t addr) {
    asm volatile("ldmatrix.sync.aligned.m8n8.x4.shared.b16 {%0,%1,%2,%3}, [%4];"
        : "=r"(r[0]), "=r"(r[1]), "=r"(r[2]), "=r"(r[3]) : "r"(addr));
}
__device__ __forceinline__ void ldsm4t(uint32_t* r, uint32_t addr) {
    asm volatile("ldmatrix.sync.aligned.m8n8.x4.trans.shared.b16 {%0,%1,%2,%3}, [%4];"
        : "=r"(r[0]), "=r"(r[1]), "=r"(r[2]), "=r"(r[3]) : "r"(addr));
}
__device__ __forceinline__ void stsm4(uint32_t addr, const uint32_t* r) {
    asm volatile("stmatrix.sync.aligned.m8n8.x4.shared.b16 [%0], {%1,%2,%3,%4};"
        :: "r"(addr), "r"(r[0]), "r"(r[1]), "r"(r[2]), "r"(r[3]) : "memory");
}
__device__ __forceinline__ void mma16816(float* c, const uint32_t* a, const uint32_t* b) {
    asm volatile("mma.sync.aligned.m16n8k16.row.col.f32.f16.f16.f32 "
        "{%0,%1,%2,%3}, {%4,%5,%6,%7}, {%8,%9}, {%0,%1,%2,%3};"
        : "+f"(c[0]), "+f"(c[1]), "+f"(c[2]), "+f"(c[3])
        : "r"(a[0]), "r"(a[1]), "r"(a[2]), "r"(a[3]), "r"(b[0]), "r"(b[1]));
}

// split a,b -> (hi half2, lo half2)
__device__ __forceinline__ void split2(float a, float b, uint32_t& hi, uint32_t& lo) {
    __half2 h = __floats2half2_rn(a, b);
    float2 hf = __half22float2(h);
    __half2 l = __floats2half2_rn(a - hf.x, b - hf.y);
    hi = h2u(h); lo = h2u(l);
}

// ---------------------------------------------------------------------------
__global__ void wcvt_kernel(const float* __restrict__ mp_w) {
    int idx = blockIdx.x * blockDim.x + threadIdx.x;
    if (idx >= D * D) return;
    float v = mp_w[idx];
    g_wh[idx] = __float2half_rn(v * v);
}

__global__ void gram_cvt_kernel() {
    int idx = blockIdx.x * blockDim.x + threadIdx.x;
    if (idx >= NGRAPH * D * D / 4) return;
    float4 a = *(const float4*)(g_grams + 4 * (size_t)idx);
    float4 b = *(const float4*)(g_grams + NGRAPH * D * D + 4 * (size_t)idx);
    __half2 h01 = __floats2half2_rn(a.x + b.x, a.y + b.y);
    __half2 h23 = __floats2half2_rn(a.z + b.z, a.w + b.w);
    *(uint2*)(g_gh + 4 * (size_t)idx) = make_uint2(h2u(h01), h2u(h23));
}

// ---------------------------------------------------------------------------
// HMMA Gram kernel (fp16, 1-pass on x~): G~[g] = X~_g^T X~_g.
// 128 blocks, K=1024 each, fp32 accumulate, partial sums (no atomics).
// ---------------------------------------------------------------------------
#define GSROW 136

__global__ __launch_bounds__(256) void gram_mma_kernel(const float* __restrict__ feats) {
    __shared__ __half sXH[64 * GSROW];
    const uint32_t sbh = smem_to_u32(sXH);

    const int tid  = threadIdx.x;
    const int w    = tid >> 5;
    const int lane = tid & 31;
    const int graph = blockIdx.x >> 1;
    const int split = blockIdx.x & 1;
    const int m0   = w * 16;

    const float* Xg = feats + ((size_t)graph * LROWS + (size_t)split * 1024) * D;

    const int g   = lane >> 3;
    const int li  = lane & 7;
    const uint32_t arl  = (uint32_t)((g >> 1) * 8 + li);
    const uint32_t acol = (uint32_t)(m0 + (g & 1) * 8);
    const uint32_t brl  = (uint32_t)((g & 1) * 8 + li);
    const uint32_t bct  = (uint32_t)(g >> 1);

    float acc[16][4];
#pragma unroll
    for (int t = 0; t < 16; t++)
#pragma unroll
        for (int v = 0; v < 4; v++) acc[t][v] = 0.f;

    for (int chunk = 0; chunk < 16; chunk++) {
        const float4* xs = (const float4*)(Xg + (size_t)chunk * 64 * D);
#pragma unroll
        for (int q = 0; q < 8; q++) {
            int idx = tid + 256 * q;
            int row = idx >> 5, c4 = idx & 31;
            float4 f = xs[idx];
            __half2 h01 = __floats2half2_rn(f.x, f.y);
            __half2 h23 = __floats2half2_rn(f.z, f.w);
            uint32_t off = (uint32_t)(row * GSROW + 4 * c4) * 2;
            *(uint2*)((char*)sXH + off) = make_uint2(h2u(h01), h2u(h23));
        }
        __syncthreads();

#pragma unroll
        for (int j = 0; j < 4; j++) {
            uint32_t aoff = ((j * 16 + arl) * GSROW + acol) * 2;
            uint32_t ah[4];
            ldsm4t(ah, sbh + aoff);
#pragma unroll
            for (int tp = 0; tp < 8; tp++) {
                uint32_t boff = ((j * 16 + brl) * GSROW + (2 * tp + bct) * 8) * 2;
                uint32_t bh[4];
                ldsm4t(bh, sbh + boff);
                mma16816(acc[2 * tp],     ah, bh);
                mma16816(acc[2 * tp + 1], ah, bh + 2);
            }
        }
        __syncthreads();
    }

    float* G = g_grams + ((size_t)split * NGRAPH + graph) * D * D;
    const int ra = lane >> 2;
    const int ca = (lane & 3) * 2;
#pragma unroll
    for (int t = 0; t < 16; t++) {
        int col = t * 8 + ca;
        *(float2*)&G[(m0 + ra) * D + col]     = make_float2(acc[t][0], acc[t][1]);
        *(float2*)&G[(m0 + ra + 8) * D + col] = make_float2(acc[t][2], acc[t][3]);
    }
}

// ---------------------------------------------------------------------------
// HMMA fused match kernel (fp16) — EXACT R10 structure (measured 88.4us):
// 32 rows/block, 256 threads, 2 blocks/SM. B operands hi-only.
// Phase1: Y = X*Gh (2-pass: Xh+Xl). Products in fragment layout (ldsm/stsm).
// Phase2: num = PN*Wh (2-pass), n1 = P1h*Wh, n2 = P2h*Wh (1-pass each).
// ---------------------------------------------------------------------------
#define SROW    136
#define OFF_XH  0u          //  8704 B  -> PN hi after products (stsm in place)
#define OFF_XL  8704u       //  8704 B  -> PN lo after products
#define OFF_BH  17408u      // 34816 B  (G hi, then W hi)
#define OFF_P1H 52224u      //  8704 B
#define OFF_P2H 60928u      //  8704 B
#define SMEM_NEED 69632

__global__ __launch_bounds__(256, 2) void match_mma_kernel(
    const float* __restrict__ feats, float* __restrict__ out) {
    extern __shared__ __align__(16) char smem[];
    const uint32_t sb = smem_to_u32(smem);

    const int tid  = threadIdx.x;
    const int w    = tid >> 5;
    const int lane = tid & 31;
    const int mt   = w >> 2;       // m16 tile 0..1
    const int nq   = w & 3;        // n quarter (32 cols)
    const int r0   = blockIdx.x * 32;
    const int gi   = r0 >> 11;

    const uint2* ghp = (const uint2*)(g_gh + (size_t)(gi ^ 1) * D * D);
    const uint2* whp = (const uint2*)g_wh;

    // ---- stage X (split hi/lo): 1024 float4, 4 per thread ----
    {
        const float4* xs = (const float4*)(feats + (size_t)r0 * D);
#pragma unroll
        for (int q = 0; q < 4; q++) {
            int idx = tid + 256 * q;
            int row = idx >> 5, c4 = idx & 31;
            float4 f = xs[idx];
            uint32_t h01, l01, h23, l23;
            split2(f.x, f.y, h01, l01);
            split2(f.z, f.w, h23, l23);
            uint32_t off = (uint32_t)(row * SROW + 4 * c4) * 2;
            *(uint2*)(smem + OFF_XH + off) = make_uint2(h01, h23);
            *(uint2*)(smem + OFF_XL + off) = make_uint2(l01, l23);
        }
    }
    // ---- stage G hi: 4096 uint2, 16 per thread ----
#pragma unroll
    for (int q = 0; q < 16; q++) {
        int pi = tid + 256 * q;
        int row = pi >> 5, cp2 = pi & 31;
        uint32_t off = (uint32_t)(row * SROW + 4 * cp2) * 2;
        *(uint2*)(smem + OFF_BH + off) = ghp[pi];
    }
    __syncthreads();

    // fragment lane offsets
    const uint32_t arow = mt * 16 + (lane & 7) + ((lane >> 3) & 1) * 8;
    const uint32_t acolh = (lane >> 4) * 8;
    const int g    = lane >> 3;
    const uint32_t bnrow = (uint32_t)((g >> 1) * 8 + (lane & 7));
    const uint32_t bkoff = (uint32_t)((g & 1) * 8);

    // ---------------- Phase 1: Y = X * Gh (2-pass) ----------------
    float accY[4][4];
#pragma unroll
    for (int t = 0; t < 4; t++)
#pragma unroll
        for (int v = 0; v < 4; v++) accY[t][v] = 0.f;

#pragma unroll
    for (int j = 0; j < 8; j++) {
        uint32_t aoff = (arow * SROW + j * 16 + acolh) * 2;
        uint32_t ah[4], al[4];
        ldsm4(ah, sb + OFF_XH + aoff);
        ldsm4(al, sb + OFF_XL + aoff);
#pragma unroll
        for (int tp = 0; tp < 2; tp++) {
            uint32_t boff = (((uint32_t)(nq * 32 + tp * 16) + bnrow) * SROW + j * 16 + bkoff) * 2;
            uint32_t bh[4];
            ldsm4(bh, sb + OFF_BH + boff);
            mma16816(accY[2 * tp], ah, bh);
            mma16816(accY[2 * tp], al, bh);
            mma16816(accY[2 * tp + 1], ah, bh + 2);
            mma16816(accY[2 * tp + 1], al, bh + 2);
        }
    }
    __syncthreads();   // all warps done reading G and X fragments

    // ---- stage W hi (over G) ----
#pragma unroll
    for (int q = 0; q < 16; q++) {
        int pi = tid + 256 * q;
        int row = pi >> 5, cp2 = pi & 31;
        uint32_t off = (uint32_t)(row * SROW + 4 * cp2) * 2;
        *(uint2*)(smem + OFF_BH + off) = whp[pi];
    }

    // ---- products in fragment layout: warp's cols = X k-chunks 2nq, 2nq+1 ----
#pragma unroll
    for (int c2 = 0; c2 < 2; c2++) {
        int j = 2 * nq + c2;
        uint32_t aoff = (arow * SROW + j * 16 + acolh) * 2;
        uint32_t xh4[4], xl4[4];
        ldsm4(xh4, sb + OFF_XH + aoff);
        ldsm4(xl4, sb + OFF_XL + aoff);

        uint32_t pnh[4], pnl[4], p1h[4], p2h[4];
#pragma unroll
        for (int q = 0; q < 4; q++) {
            int t  = 2 * c2 + (q >> 1);       // n8 tile
            int rv = (q & 1) * 2;             // 0: rows r, 2: rows r+8
            float2 xhf = __half22float2(*(__half2*)&xh4[q]);
            float2 xlf = __half22float2(*(__half2*)&xl4[q]);
            float x0 = xhf.x + xlf.x;
            float x1 = xhf.y + xlf.y;
            float y0 = accY[t][rv]     * YSCALE;
            float y1 = accY[t][rv + 1] * YSCALE;
            split2(x0 * y0, x1 * y1, pnh[q], pnl[q]);
            p1h[q] = h2u(__floats2half2_rn(x0 * x0, x1 * x1));
            p2h[q] = h2u(__floats2half2_rn(y0 * y0, y1 * y1));
        }
        stsm4(sb + OFF_XH + aoff, pnh);    // PN hi in place over X hi
        stsm4(sb + OFF_XL + aoff, pnl);    // PN lo in place over X lo
        stsm4(sb + OFF_P1H + aoff, p1h);
        stsm4(sb + OFF_P2H + aoff, p2h);
    }
    __syncthreads();

    // ---------------- Phase 2: num 2-pass, n1 1-pass, n2 1-pass ----------
    float accN[4][4], accB[4][4], accC[4][4];
#pragma unroll
    for (int t = 0; t < 4; t++)
#pragma unroll
        for (int v = 0; v < 4; v++) { accN[t][v] = 0.f; accB[t][v] = 0.f; accC[t][v] = 0.f; }

#pragma unroll
    for (int j = 0; j < 8; j++) {
        uint32_t aoff = (arow * SROW + j * 16 + acolh) * 2;
        uint32_t n_h[4], n_l[4], p1[4], p2[4];
        ldsm4(n_h, sb + OFF_XH + aoff);
        ldsm4(n_l, sb + OFF_XL + aoff);
        ldsm4(p1,  sb + OFF_P1H + aoff);
        ldsm4(p2,  sb + OFF_P2H + aoff);
#pragma unroll
        for (int tp = 0; tp < 2; tp++) {
            uint32_t boff = (((uint32_t)(nq * 32 + tp * 16) + bnrow) * SROW + j * 16 + bkoff) * 2;
            uint32_t wh_[4];
            ldsm4(wh_, sb + OFF_BH + boff);
            mma16816(accN[2 * tp], n_h, wh_);
            mma16816(accN[2 * tp], n_l, wh_);
            mma16816(accB[2 * tp], p1, wh_);
            mma16816(accC[2 * tp], p2, wh_);
            mma16816(accN[2 * tp + 1], n_h, wh_ + 2);
            mma16816(accN[2 * tp + 1], n_l, wh_ + 2);
            mma16816(accB[2 * tp + 1], p1, wh_ + 2);
            mma16816(accC[2 * tp + 1], p2, wh_ + 2);
        }
    }

    // ---------------- Epilogue ----------------
    const int ra = lane >> 2;
    const int ca = (lane & 3) * 2;
#pragma unroll
    for (int t = 0; t < 4; t++) {
        int col = nq * 32 + t * 8 + ca;
#pragma unroll
        for (int h2 = 0; h2 < 2; h2++) {
            int row = r0 + mt * 16 + ra + 8 * h2;
            float n0v = accN[t][2 * h2], n1v = accN[t][2 * h2 + 1];
            float b0v = accB[t][2 * h2], b1v = accB[t][2 * h2 + 1];
            float c0v = accC[t][2 * h2], c1v = accC[t][2 * h2 + 1];
            float2 o;
            o.x = n0v / fmaxf(sqrtf(b0v * c0v), EPS);
            o.y = n1v / fmaxf(sqrtf(b1v * c1v), EPS);
            *(float2*)(out + (size_t)row * D + col) = o;
        }
    }
}

// ---------------------------------------------------------------------------
extern "C" void kernel_launch(void* const* d_in, const int* in_sizes, int n_in,
                              void* d_out, int out_size) {
    const float* feats = (const float*)d_in[0];
    const float* mp_w  = (const float*)d_in[1];
    float* out = (float*)d_out;

    static bool attr_done = false;
    if (!attr_done) {
        cudaFuncSetAttribute(match_mma_kernel,
                             cudaFuncAttributeMaxDynamicSharedMemorySize, SMEM_NEED);
        attr_done = true;
    }

    int N = in_sizes[0] / D;   // 131072 rows

    wcvt_kernel<<<(D * D + 255) / 256, 256>>>(mp_w);
    gram_mma_kernel<<<NGRAPH * 2, 256>>>(feats);
    gram_cvt_kernel<<<(NGRAPH * D * D / 4 + 255) / 256, 256>>>();
    match_mma_kernel<<<N / 32, 256, SMEM_NEED>>>(feats, out);
}